// round 1
// baseline (speedup 1.0000x reference)
#include <cuda_runtime.h>
#include <cstdint>

// Problem constants
#define NB     16
#define NFREQ  513
#define NT     4000
#define NFFT   1024
#define HOP    256
#define OUT_PER_B (3999 * 256)   // 1023744

#define FPB    8                 // frames per block (one warp each)
#define THREADS 256

// 262 MB frames scratch (windowed frames, [B*T, 1024] f32)
__device__ float g_frames[(size_t)NB * NT * NFFT];

// ---------------------------------------------------------------------------
// complex helpers
// ---------------------------------------------------------------------------
__device__ __forceinline__ float2 cmul(float2 a, float2 b) {
    return make_float2(a.x * b.x - a.y * b.y, a.x * b.y + a.y * b.x);
}

// W32^t = e^{+2*pi*i*t/32}, t = 0..15
__device__ __constant__ float W32C[16] = {
    1.0f, 0.98078528f, 0.92387953f, 0.83146961f,
    0.70710678f, 0.55557023f, 0.38268343f, 0.19509032f,
    0.0f, -0.19509032f, -0.38268343f, -0.55557023f,
    -0.70710678f, -0.83146961f, -0.92387953f, -0.98078528f
};
__device__ __constant__ float W32S[16] = {
    0.0f, 0.19509032f, 0.38268343f, 0.55557023f,
    0.70710678f, 0.83146961f, 0.92387953f, 0.98078528f,
    1.0f, 0.98078528f, 0.92387953f, 0.83146961f,
    0.70710678f, 0.55557023f, 0.38268343f, 0.19509032f
};

// 32-point IDFT in registers (no 1/N): out[m] = sum_j in[j] * e^{+2pi i j m / 32}
__device__ __forceinline__ void ifft32(float2 v[32]) {
    float2 t[32];
    // bit-reverse (5 bits) permute input
#pragma unroll
    for (int i = 0; i < 32; i++) {
        int r = ((i & 1) << 4) | ((i & 2) << 2) | (i & 4) | ((i & 8) >> 2) | ((i & 16) >> 4);
        t[i] = v[r];
    }
#pragma unroll
    for (int i = 0; i < 32; i++) v[i] = t[i];
    // DIT butterflies with e^{+i...} twiddles
#pragma unroll
    for (int s = 1; s <= 5; s++) {
        const int len  = 1 << s;
        const int half = len >> 1;
        const int step = 32 >> s;
#pragma unroll
        for (int i = 0; i < 32; i += len) {
#pragma unroll
            for (int j = 0; j < half; j++) {
                float2 w = make_float2(W32C[j * step], W32S[j * step]);
                float2 u = v[i + j];
                float2 q = cmul(v[i + j + half], w);
                v[i + j]        = make_float2(u.x + q.x, u.y + q.y);
                v[i + j + half] = make_float2(u.x - q.x, u.y - q.y);
            }
        }
    }
}

// ---------------------------------------------------------------------------
// Pass 1: per-frame irfft + window  -> g_frames
// smem layout: float2 spec[FPB][1056] | float2 tw[1024] | float win[1024]
// ---------------------------------------------------------------------------
#define SPEC_STRIDE 1056  // float2 per frame region (>= 31*33+31+1 for transpose)
#define SMEM_BYTES (FPB * SPEC_STRIDE * 8 + 1024 * 8 + 1024 * 4)

__global__ void __launch_bounds__(THREADS, 2)
istft_frames_kernel(const float* __restrict__ mag,
                    const float* __restrict__ cosp,
                    const float* __restrict__ sinp,
                    const float* __restrict__ window) {
    extern __shared__ float smem_raw[];
    float2* spec = reinterpret_cast<float2*>(smem_raw);
    float2* tw   = spec + FPB * SPEC_STRIDE;
    float*  win  = reinterpret_cast<float*>(tw + 1024);

    const int tid = threadIdx.x;

    // init twiddle table e^{+2pi i j/1024} and window copy
    for (int j = tid; j < 1024; j += THREADS) {
        float sv, cv;
        sincosf(6.283185307179586f * (float)j * (1.0f / 1024.0f), &sv, &cv);
        tw[j]  = make_float2(cv, sv);
        win[j] = window[j];
    }

    // load spectrum, build full Hermitian 1024-pt complex spectrum per frame
    const int frame0 = blockIdx.x * FPB;
    const int b  = frame0 / NT;
    const int t0 = frame0 % NT;
    const size_t base = (size_t)b * NFREQ * NT + t0;
    const int t_off = tid & 7;     // 8 consecutive t -> one 32B sector
    const int f_off = tid >> 3;    // 32 f values in flight

    float2* Sld = spec + t_off * SPEC_STRIDE;
    for (int f = f_off; f < NFREQ; f += 32) {
        size_t idx = base + (size_t)f * NT + t_off;
        float m  = mag[idx];
        float cp = cosp[idx];
        float sp = sinp[idx];
        float hr = m * cp;
        float hi = m * sp;
        Sld[f] = make_float2(hr, hi);
        if (f >= 1 && f <= 511) Sld[1024 - f] = make_float2(hr, -hi);
    }
    __syncthreads();

    // one warp per frame: 1024-pt IDFT as 32x32 four-step
    const int w    = tid >> 5;
    const int lane = tid & 31;
    float2* S = spec + w * SPEC_STRIDE;

    float2 v[32];
#pragma unroll
    for (int r = 0; r < 32; r++) v[r] = S[lane + 32 * r];   // lane = k1, reg = k2

    ifft32(v);                                              // reg index -> n1

#pragma unroll
    for (int n1 = 0; n1 < 32; n1++) v[n1] = cmul(v[n1], tw[n1 * lane]);

    __syncwarp();
#pragma unroll
    for (int n1 = 0; n1 < 32; n1++) S[n1 * 33 + lane] = v[n1];  // padded transpose
    __syncwarp();
#pragma unroll
    for (int j = 0; j < 32; j++) v[j] = S[lane * 33 + j];   // lane = n1, reg = k1

    ifft32(v);                                              // reg index -> n2

    __syncwarp();
    float* out_s = reinterpret_cast<float*>(S);
    const float inv_n = 1.0f / 1024.0f;
#pragma unroll
    for (int n2 = 0; n2 < 32; n2++) {
        int n = lane + 32 * n2;
        out_s[n] = v[n2].x * win[n] * inv_n;                // Re(iDFT) * window
    }
    __syncthreads();

    // coalesced float4 store of all 8 frames
#pragma unroll
    for (int fr = 0; fr < FPB; fr++) {
        const float4* src = reinterpret_cast<const float4*>(
            reinterpret_cast<const float*>(spec + fr * SPEC_STRIDE));
        float4* dst = reinterpret_cast<float4*>(
            g_frames + (size_t)(frame0 + fr) * NFFT);
        dst[tid] = src[tid];
    }
}

// ---------------------------------------------------------------------------
// Pass 2: gather overlap-add + envelope normalize + trim
// grid = (3999, 16), block = 256 ; one output sample per thread
// ---------------------------------------------------------------------------
__global__ void __launch_bounds__(256)
overlap_add_kernel(const float* __restrict__ window,
                   float* __restrict__ out) {
    const int b = blockIdx.y;
    const int j = blockIdx.x * 256 + threadIdx.x;     // [0, OUT_PER_B)
    const int s = j + NFFT / 2;                       // global sample index

    int tmax = s >> 8;
    if (tmax > NT - 1) tmax = NT - 1;
    int tmin = (s - 768) >> 8;                        // floor((s-1023+255)/256)
    if (tmin < 0) tmin = 0;

    const float* fb = g_frames + (size_t)b * NT * NFFT;
    float acc = 0.0f, env = 0.0f;
#pragma unroll 4
    for (int t = tmin; t <= tmax; t++) {
        int n = s - (t << 8);
        acc += fb[(size_t)t * NFFT + n];
        float wv = window[n];
        env += wv * wv;
    }
    out[(size_t)b * OUT_PER_B + j] = acc / (env + 1e-11f);
}

// ---------------------------------------------------------------------------
extern "C" void kernel_launch(void* const* d_in, const int* in_sizes, int n_in,
                              void* d_out, int out_size) {
    const float* mag    = (const float*)d_in[0];
    const float* cosp   = (const float*)d_in[1];
    const float* sinp   = (const float*)d_in[2];
    const float* window = (const float*)d_in[3];
    float* out = (float*)d_out;

    cudaFuncSetAttribute(istft_frames_kernel,
                         cudaFuncAttributeMaxDynamicSharedMemorySize, SMEM_BYTES);

    const int n_frames = NB * NT;                  // 64000
    istft_frames_kernel<<<n_frames / FPB, THREADS, SMEM_BYTES>>>(mag, cosp, sinp, window);

    dim3 grid2(OUT_PER_B / 256, NB);               // 3999 x 16, exact
    overlap_add_kernel<<<grid2, 256>>>(window, out);
}

// round 2
// speedup vs baseline: 2.0088x; 2.0088x over previous
#include <cuda_runtime.h>
#include <cstdint>

// Problem constants
#define NB     16
#define NFREQ  513
#define NT     4000
#define NFFT   1024
#define HOP    256
#define OUT_PER_B (3999 * 256)   // 1023744

#define THREADS 256
#define FPB     8                // frames per block (one warp each)
#define SP_STRIDE 522            // float2 stride per frame spectrum (bank-friendly)

// 262 MB frames scratch (windowed frames, [B*T, 1024] f32)
__device__ float g_frames[(size_t)NB * NT * NFFT];
// Twiddle table e^{+2*pi*i*j/1024}, j = 0..1023
__device__ float2 g_tw[1024];

// e^{+2*pi*i*j/32}
__constant__ float W32C[32] = {
     1.000000000f,  0.980785280f,  0.923879533f,  0.831469612f,
     0.707106781f,  0.555570233f,  0.382683432f,  0.195090322f,
     0.000000000f, -0.195090322f, -0.382683432f, -0.555570233f,
    -0.707106781f, -0.831469612f, -0.923879533f, -0.980785280f,
    -1.000000000f, -0.980785280f, -0.923879533f, -0.831469612f,
    -0.707106781f, -0.555570233f, -0.382683432f, -0.195090322f,
     0.000000000f,  0.195090322f,  0.382683432f,  0.555570233f,
     0.707106781f,  0.831469612f,  0.923879533f,  0.980785280f
};
__constant__ float W32S[32] = {
     0.000000000f,  0.195090322f,  0.382683432f,  0.555570233f,
     0.707106781f,  0.831469612f,  0.923879533f,  0.980785280f,
     1.000000000f,  0.980785280f,  0.923879533f,  0.831469612f,
     0.707106781f,  0.555570233f,  0.382683432f,  0.195090322f,
     0.000000000f, -0.195090322f, -0.382683432f, -0.555570233f,
    -0.707106781f, -0.831469612f, -0.923879533f, -0.980785280f,
    -1.000000000f, -0.980785280f, -0.923879533f, -0.831469612f,
    -0.707106781f, -0.555570233f, -0.382683432f, -0.195090322f
};

__global__ void tw_init_kernel() {
    int j = blockIdx.x * 256 + threadIdx.x;   // grid covers 1024
    if (j < 1024) {
        float s, c;
        sincospif((float)j * (1.0f / 512.0f), &s, &c);   // 2*pi*j/1024
        g_tw[j] = make_float2(c, s);
    }
}

// ---------------------------------------------------------------------------
// 16-point inverse DFT in registers (radix-4 x radix-4), no 1/N scaling.
// In/out: v[j] -> y[m] = sum_j v[j] e^{+2*pi*i*j*m/16}, stored at v[m].
// ---------------------------------------------------------------------------
__device__ __forceinline__ void ifft16(float2 v[16]) {
    float2 g[16];
#pragma unroll
    for (int j1 = 0; j1 < 4; j1++) {
        float2 a = v[j1], b = v[j1 + 4], c = v[j1 + 8], d = v[j1 + 12];
        float t0x = a.x + c.x, t0y = a.y + c.y;
        float t1x = a.x - c.x, t1y = a.y - c.y;
        float t2x = b.x + d.x, t2y = b.y + d.y;
        float t3x = b.x - d.x, t3y = b.y - d.y;
        g[j1 * 4 + 0] = make_float2(t0x + t2x, t0y + t2y);
        g[j1 * 4 + 1] = make_float2(t1x - t3y, t1y + t3x);   // + i*t3
        g[j1 * 4 + 2] = make_float2(t0x - t2x, t0y - t2y);
        g[j1 * 4 + 3] = make_float2(t1x + t3y, t1y - t3x);   // - i*t3
    }
    // twiddle: g[j1*4+m2] *= e^{2*pi*i*j1*m2/16} = W32[2*j1*m2]
#pragma unroll
    for (int j1 = 1; j1 < 4; j1++) {
#pragma unroll
        for (int m2 = 1; m2 < 4; m2++) {
            float wc = W32C[2 * j1 * m2];
            float ws = W32S[2 * j1 * m2];
            float2 x = g[j1 * 4 + m2];
            g[j1 * 4 + m2] = make_float2(x.x * wc - x.y * ws, x.x * ws + x.y * wc);
        }
    }
#pragma unroll
    for (int m2 = 0; m2 < 4; m2++) {
        float2 a = g[m2], b = g[4 + m2], c = g[8 + m2], d = g[12 + m2];
        float t0x = a.x + c.x, t0y = a.y + c.y;
        float t1x = a.x - c.x, t1y = a.y - c.y;
        float t2x = b.x + d.x, t2y = b.y + d.y;
        float t3x = b.x - d.x, t3y = b.y - d.y;
        v[m2 + 0]  = make_float2(t0x + t2x, t0y + t2y);
        v[m2 + 4]  = make_float2(t1x - t3y, t1y + t3x);
        v[m2 + 8]  = make_float2(t0x - t2x, t0y - t2y);
        v[m2 + 12] = make_float2(t1x + t3y, t1y - t3x);
    }
}

// ---------------------------------------------------------------------------
// Pass 1: per-frame irfft (via 512-pt complex IFFT) + window -> g_frames
// One warp per frame, 8 frames per block.
// ---------------------------------------------------------------------------
__global__ void __launch_bounds__(THREADS, 2)
istft_frames_kernel(const float* __restrict__ mag,
                    const float* __restrict__ cosp,
                    const float* __restrict__ sinp,
                    const float* __restrict__ window) {
    __shared__ float2 sp[FPB * SP_STRIDE];   // H spectra, 513 per frame
    __shared__ float2 tw[1024];              // e^{2*pi*i*j/1024}
    __shared__ float  win_s[1024 + 32];      // padded window

    const int tid = threadIdx.x;

    for (int j = tid; j < 1024; j += THREADS) {
        tw[j] = g_tw[j];
        win_s[j + (j >> 5)] = window[j];
    }

    // cooperative coalesced load: 8 consecutive t per 32B sector
    const int frame0 = blockIdx.x * FPB;
    const int b  = frame0 / NT;
    const int t0 = frame0 % NT;
    const size_t base = (size_t)b * NFREQ * NT + t0;
    const int t_off = tid & 7;
    const int f_off = tid >> 3;

    float2* Sld = sp + t_off * SP_STRIDE;
    for (int f = f_off; f < NFREQ; f += 32) {
        size_t idx = base + (size_t)f * NT + t_off;
        float m  = mag[idx];
        float cp = cosp[idx];
        float sn = sinp[idx];
        Sld[f] = make_float2(m * cp, m * sn);
    }
    __syncthreads();

    const int w    = tid >> 5;
    const int lane = tid & 31;
    const float2* H = sp + w * SP_STRIDE;

    // Build Z[k] = (H[k]+conj(H[512-k])) + i*W1024^k*(H[k]-conj(H[512-k]))
    // lane holds k = lane + 32*k2, k2 = 0..15
    float2 v[16];
#pragma unroll
    for (int k2 = 0; k2 < 16; k2++) {
        const int k = lane + (k2 << 5);
        float2 a  = H[k];
        float2 bb = H[512 - k];
        if (k == 0) { a.y = 0.0f; bb.y = 0.0f; }   // realness fix at DC/Nyquist
        float qx = a.x - bb.x;
        float qy = a.y + bb.y;
        float2 W = tw[k];
        v[k2].x = (a.x + bb.x) - (W.x * qy + W.y * qx);
        v[k2].y = (a.y - bb.y) + (W.x * qx - W.y * qy);
    }

    // 16-pt IDFT over k2 -> n2
    ifft16(v);

    // twiddle e^{2*pi*i*n2*lane/512} = tw[2*n2*lane]
#pragma unroll
    for (int n2 = 1; n2 < 16; n2++) {
        float2 W = tw[(2 * n2 * lane) & 1023];
        float2 x = v[n2];
        v[n2] = make_float2(x.x * W.x - x.y * W.y, x.x * W.y + x.y * W.x);
    }

    // cross-lane 32-pt inverse DIF over k1 (lanes); result lane holds n1=bitrev5(lane)
#pragma unroll
    for (int s = 0; s < 5; s++) {
        const int h = 16 >> s;
        const float wc = W32C[(lane & (h - 1)) << s];
        const float ws = W32S[(lane & (h - 1)) << s];
        const bool hi = (lane & h) != 0;
#pragma unroll
        for (int n2 = 0; n2 < 16; n2++) {
            float px = __shfl_xor_sync(0xffffffffu, v[n2].x, h);
            float py = __shfl_xor_sync(0xffffffffu, v[n2].y, h);
            float2 r;
            if (hi) {
                float dx = px - v[n2].x;
                float dy = py - v[n2].y;
                r = make_float2(dx * wc - dy * ws, dx * ws + dy * wc);
            } else {
                r = make_float2(v[n2].x + px, v[n2].y + py);
            }
            v[n2] = r;
        }
    }

    const int n1 = __brev(lane) >> 27;   // bitrev5
    // lane owns samples x[32*n1 + 2*n2 (+1)] = Re/Im of y[16*n1+n2]
    float* dst = g_frames + (size_t)(frame0 + w) * NFFT + 32 * n1;
    const float inv_n = 1.0f / 1024.0f;
#pragma unroll
    for (int q = 0; q < 8; q++) {
        const int nb = 32 * n1 + 4 * q;
        float w0 = win_s[nb + 0 + n1];
        float w1 = win_s[nb + 1 + n1];
        float w2 = win_s[nb + 2 + n1];
        float w3 = win_s[nb + 3 + n1];
        float4 o;
        o.x = v[2 * q].x     * w0 * inv_n;
        o.y = v[2 * q].y     * w1 * inv_n;
        o.z = v[2 * q + 1].x * w2 * inv_n;
        o.w = v[2 * q + 1].y * w3 * inv_n;
        *reinterpret_cast<float4*>(dst + 4 * q) = o;
    }
}

// ---------------------------------------------------------------------------
// Pass 2: gather overlap-add + envelope normalize + trim (4 samples/thread)
// ---------------------------------------------------------------------------
__global__ void __launch_bounds__(256)
overlap_add_kernel(const float* __restrict__ window,
                   float* __restrict__ out) {
    const int b  = blockIdx.y;
    const int j4 = blockIdx.x * 256 + threadIdx.x;
    if (j4 >= OUT_PER_B / 4) return;
    const int s0 = 4 * j4 + NFFT / 2;

    int thi = s0 >> 8; if (thi > NT - 1) thi = NT - 1;
    int tmp = s0 - 765;                        // ceil((s0-1020)/256)
    int tlo = tmp > 0 ? (tmp >> 8) : 0;

    const float* fb = g_frames + (size_t)b * NT * NFFT;
    float4 acc = make_float4(0.f, 0.f, 0.f, 0.f);
    float4 env = make_float4(0.f, 0.f, 0.f, 0.f);
#pragma unroll 5
    for (int t = tlo; t <= thi; t++) {
        const int n0 = s0 - (t << 8);          // in [0,1020], %4==0
        float4 f  = *reinterpret_cast<const float4*>(fb + (size_t)t * NFFT + n0);
        float4 wv = *reinterpret_cast<const float4*>(window + n0);
        acc.x += f.x; acc.y += f.y; acc.z += f.z; acc.w += f.w;
        env.x += wv.x * wv.x; env.y += wv.y * wv.y;
        env.z += wv.z * wv.z; env.w += wv.w * wv.w;
    }
    float4 r;
    r.x = acc.x / (env.x + 1e-11f);
    r.y = acc.y / (env.y + 1e-11f);
    r.z = acc.z / (env.z + 1e-11f);
    r.w = acc.w / (env.w + 1e-11f);
    *reinterpret_cast<float4*>(out + (size_t)b * OUT_PER_B + 4 * j4) = r;
}

// ---------------------------------------------------------------------------
extern "C" void kernel_launch(void* const* d_in, const int* in_sizes, int n_in,
                              void* d_out, int out_size) {
    const float* mag    = (const float*)d_in[0];
    const float* cosp   = (const float*)d_in[1];
    const float* sinp   = (const float*)d_in[2];
    const float* window = (const float*)d_in[3];
    float* out = (float*)d_out;

    tw_init_kernel<<<4, 256>>>();

    const int n_frames = NB * NT;                       // 64000
    istft_frames_kernel<<<n_frames / FPB, THREADS>>>(mag, cosp, sinp, window);

    dim3 grid2((OUT_PER_B / 4 + 255) / 256, NB);        // 1000 x 16
    overlap_add_kernel<<<grid2, 256>>>(window, out);
}